// round 17
// baseline (speedup 1.0000x reference)
#include <cuda_runtime.h>
#include <cuda_bf16.h>
#include <cuda_fp16.h>
#include <math.h>
#include <stdint.h>

#define BATCH 2
#define SEQ   4096
#define DMODEL 512
#define NHEAD 8
#define HDIM  64
#define MROWS (BATCH*SEQ)
#define MAXREL 2
#define LOG2E 1.44269504f

typedef unsigned long long ull;

// scratch
__device__ unsigned short g_Qh[MROWS * DMODEL];       // fp16 (Q, pre-scaled 0.125*log2e)
__device__ unsigned short g_Kh[MROWS * DMODEL];       // fp16
__device__ unsigned short g_Vh[MROWS * DMODEL];       // fp16
__device__ unsigned short g_Ih[3 * MROWS * DMODEL];   // bf16 hi of q,k,v inputs
__device__ unsigned short g_Il[3 * MROWS * DMODEL];   // bf16 lo
__device__ unsigned short g_WhA[4 * DMODEL * DMODEL]; // bf16 hi of Wq,Wk,Wv,Wo
__device__ unsigned short g_WlA[4 * DMODEL * DMODEL]; // bf16 lo
__device__ unsigned short g_Ah[MROWS * DMODEL];       // bf16 hi of attn out
__device__ unsigned short g_Al[MROWS * DMODEL];       // bf16 lo

__device__ __forceinline__ void split2(float a, float b, uint32_t& h, uint32_t& l) {
    asm("cvt.rn.bf16x2.f32 %0, %1, %2;" : "=r"(h) : "f"(b), "f"(a));
    float ha = __uint_as_float(h << 16);
    float hb = __uint_as_float(h & 0xffff0000u);
    float ra = a - ha, rb = b - hb;
    asm("cvt.rn.bf16x2.f32 %0, %1, %2;" : "=r"(l) : "f"(rb), "f"(ra));
}
__device__ __forceinline__ uint32_t pkhf2(float a, float b) {
    uint32_t h;
    asm("cvt.rn.f16x2.f32 %0, %1, %2;" : "=r"(h) : "f"(b), "f"(a));
    return h;
}
__device__ __forceinline__ float ex2f(float x) {
    float y; asm("ex2.approx.f32 %0, %1;" : "=f"(y) : "f"(x)); return y;
}

static __device__ __forceinline__ uint32_t smem_u32(const void* p) {
    uint32_t a;
    asm("{ .reg .u64 t; cvta.to.shared.u64 t, %1; cvt.u32.u64 %0, t; }" : "=r"(a) : "l"(p));
    return a;
}
__device__ __forceinline__ void ldsm4(uint32_t* r, uint32_t addr) {
    asm volatile("ldmatrix.sync.aligned.m8n8.x4.shared.b16 {%0,%1,%2,%3}, [%4];"
                 : "=r"(r[0]), "=r"(r[1]), "=r"(r[2]), "=r"(r[3]) : "r"(addr));
}
__device__ __forceinline__ void ldsm4t(uint32_t* r, uint32_t addr) {
    asm volatile("ldmatrix.sync.aligned.m8n8.x4.trans.shared.b16 {%0,%1,%2,%3}, [%4];"
                 : "=r"(r[0]), "=r"(r[1]), "=r"(r[2]), "=r"(r[3]) : "r"(addr));
}
__device__ __forceinline__ void mmabf16(float* c, const uint32_t* a, uint32_t b0, uint32_t b1) {
    asm volatile("mma.sync.aligned.m16n8k16.row.col.f32.bf16.bf16.f32 "
                 "{%0,%1,%2,%3}, {%4,%5,%6,%7}, {%8,%9}, {%0,%1,%2,%3};"
                 : "+f"(c[0]), "+f"(c[1]), "+f"(c[2]), "+f"(c[3])
                 : "r"(a[0]), "r"(a[1]), "r"(a[2]), "r"(a[3]), "r"(b0), "r"(b1));
}
__device__ __forceinline__ void mmaf16(float* c, const uint32_t* a, uint32_t b0, uint32_t b1) {
    asm volatile("mma.sync.aligned.m16n8k16.row.col.f32.f16.f16.f32 "
                 "{%0,%1,%2,%3}, {%4,%5,%6,%7}, {%8,%9}, {%0,%1,%2,%3};"
                 : "+f"(c[0]), "+f"(c[1]), "+f"(c[2]), "+f"(c[3])
                 : "r"(a[0]), "r"(a[1]), "r"(a[2]), "r"(a[3]), "r"(b0), "r"(b1));
}
__device__ __forceinline__ void cpa16(uint32_t d, const void* s) {
    asm volatile("cp.async.cg.shared.global [%0], [%1], 16;" :: "r"(d), "l"(s));
}
#define CP_COMMIT() asm volatile("cp.async.commit_group;" ::: "memory")
#define CP_WAIT2()  asm volatile("cp.async.wait_group 2;" ::: "memory")

#define SW128(o) ((o) ^ (((o) >> 3) & 0x70))
#define SW64(o)  ((o) ^ (((o) >> 3) & 0x30))

// ---------------------------------------------------------------------------
// Pre-split kernels
// ---------------------------------------------------------------------------
__global__ __launch_bounds__(256) void split_x3(const float* __restrict__ q,
                                                const float* __restrict__ k,
                                                const float* __restrict__ v)
{
    const float* srcs[3] = {q, k, v};
    const int sel = blockIdx.y;
    const size_t i = (size_t)blockIdx.x * 256 + threadIdx.x;
    float4 x = ((const float4*)srcs[sel])[i];
    uint2 h, l;
    split2(x.x, x.y, h.x, l.x);
    split2(x.z, x.w, h.y, l.y);
    ((uint2*)(g_Ih + (size_t)sel * MROWS * DMODEL))[i] = h;
    ((uint2*)(g_Il + (size_t)sel * MROWS * DMODEL))[i] = l;
}

__global__ __launch_bounds__(256) void split_w4(const float* __restrict__ W0,
                                                const float* __restrict__ W1,
                                                const float* __restrict__ W2,
                                                const float* __restrict__ W3)
{
    const float* srcs[4] = {W0, W1, W2, W3};
    const int sel = blockIdx.y;
    const size_t i = (size_t)blockIdx.x * 256 + threadIdx.x;
    float4 x = ((const float4*)srcs[sel])[i];
    uint2 h, l;
    split2(x.x, x.y, h.x, l.x);
    split2(x.z, x.w, h.y, l.y);
    ((uint2*)(g_WhA + (size_t)sel * DMODEL * DMODEL))[i] = h;
    ((uint2*)(g_WlA + (size_t)sel * DMODEL * DMODEL))[i] = l;
}

// ---------------------------------------------------------------------------
// Tensor-core GEMM on pre-split bf16 hi/lo, 4-stage BK=16 cp.async ring
// (power-of-2 indexing + WAIT2, mirroring the proven attn pipeline).
// Stage = XH 4K | XL 4K | WH 4K | WL 4K = 16KB; 4 stages = 64KB.
// qkv mode: blockIdx.z in {0,1,2} selects input/weight/output (fp16 out).
// o mode (qkv=0 path): fp32 out.
// ---------------------------------------------------------------------------
#define GEMM_SMEM 65536
#define GSTG 16384
#define GXH 0
#define GXL 4096
#define GWH 8192
#define GWL 12288
#define GNK (DMODEL / 16)   /* 32 chunks */

__device__ __forceinline__ void gemm_core(const unsigned short* Xh, const unsigned short* Xl,
                                          const unsigned short* Wh, const unsigned short* Wl,
                                          const float* bias,
                                          float* Cf, unsigned short* Ch,
                                          float scale, int mode,
                                          int m0, int n0, char* gsm)
{
    const uint32_t sb = smem_u32(gsm);
    const int tid = threadIdx.x;
    const int w = tid >> 5;
    const int lane = tid & 31;

    // loader: 256 threads cover one 128x16-element (32B/row) array per stage:
    // each thread: 2 arrays' rows? Layout: rows 128, 32B each = 4096B -> 256 threads x 16B.
    const int lrow = tid >> 1;          // 0..127
    const int lhalf = tid & 1;          // which 16B of the 32B row
    const size_t xrow = (size_t)(m0 + lrow) * DMODEL + lhalf * 8;
    const size_t wrow = (size_t)(n0 + lrow) * DMODEL + lhalf * 8;
    const uint32_t soff = SW64((uint32_t)(lrow * 32 + lhalf * 16));

    // ldmatrix bases, row stride 32B
    const uint32_t base_a = (uint32_t)((16 * w + (lane & 15)) * 32 + (lane >> 4) * 16);
    const uint32_t base_b = (uint32_t)(((lane & 7) + ((lane & 16) >> 1)) * 32 + ((lane >> 3) & 1) * 16);

    float cs[16][4];
#pragma unroll
    for (int i = 0; i < 16; i++)
#pragma unroll
        for (int j = 0; j < 4; j++) cs[i][j] = 0.f;

    // prologue: stages 0..2
#pragma unroll
    for (int s = 0; s < 3; s++) {
        const uint32_t st = sb + s * GSTG;
        const size_t gk = (size_t)(s * 16);
        cpa16(st + GXH + soff, Xh + xrow + gk);
        cpa16(st + GXL + soff, Xl + xrow + gk);
        cpa16(st + GWH + soff, Wh + wrow + gk);
        cpa16(st + GWL + soff, Wl + wrow + gk);
        CP_COMMIT();
    }

    for (int ks = 0; ks < GNK; ks++) {
        CP_WAIT2();
        __syncthreads();

        if (ks + 3 < GNK) {
            const uint32_t st = sb + ((ks + 3) & 3) * GSTG;
            const size_t gk = (size_t)((ks + 3) * 16);
            cpa16(st + GXH + soff, Xh + xrow + gk);
            cpa16(st + GXL + soff, Xl + xrow + gk);
            cpa16(st + GWH + soff, Wh + wrow + gk);
            cpa16(st + GWL + soff, Wl + wrow + gk);
        }
        CP_COMMIT();

        const uint32_t bp = sb + (uint32_t)(ks & 3) * GSTG;
        uint32_t ah[4], al[4];
        ldsm4(ah, bp + GXH + SW64(base_a));
        ldsm4(al, bp + GXL + SW64(base_a));
#pragma unroll
        for (int j2 = 0; j2 < 8; j2++) {
            uint32_t bh[4], bl[4];
            const uint32_t boff = SW64(base_b + 512u * j2);
            ldsm4(bh, bp + GWH + boff);
            ldsm4(bl, bp + GWL + boff);
            mmabf16(cs[2 * j2], ah, bh[0], bh[1]);
            mmabf16(cs[2 * j2], ah, bl[0], bl[1]);
            mmabf16(cs[2 * j2], al, bh[0], bh[1]);
            mmabf16(cs[2 * j2 + 1], ah, bh[2], bh[3]);
            mmabf16(cs[2 * j2 + 1], ah, bl[2], bl[3]);
            mmabf16(cs[2 * j2 + 1], al, bh[2], bh[3]);
        }
    }

    const int rr = m0 + 16 * w + (lane >> 2);
    const int cc = 2 * (lane & 3);
    if (mode == 0) {
#pragma unroll
        for (int t = 0; t < 16; t++) {
            const int col = n0 + 8 * t + cc;
            const float2 bv = *(const float2*)(bias + col);
            float* C0 = Cf + (size_t)rr * DMODEL + col;
            *(float2*)C0 = make_float2(cs[t][0] + bv.x, cs[t][1] + bv.y);
            *(float2*)(C0 + 8 * DMODEL) = make_float2(cs[t][2] + bv.x, cs[t][3] + bv.y);
        }
    } else {
#pragma unroll
        for (int t = 0; t < 16; t++) {
            const int col = n0 + 8 * t + cc;
            const float2 bv = *(const float2*)(bias + col);
            *(uint32_t*)(Ch + (size_t)rr * DMODEL + col) =
                pkhf2(scale * (cs[t][0] + bv.x), scale * (cs[t][1] + bv.y));
            *(uint32_t*)(Ch + (size_t)(rr + 8) * DMODEL + col) =
                pkhf2(scale * (cs[t][2] + bv.x), scale * (cs[t][3] + bv.y));
        }
    }
}

// Fused Q/K/V projection: blockIdx.z selects stream.
__global__ __launch_bounds__(256, 2) void gemm_qkv(const float* __restrict__ bq,
                                                   const float* __restrict__ bk,
                                                   const float* __restrict__ bv)
{
    extern __shared__ char gsm[];
    const int z = blockIdx.z;
    const size_t NI = (size_t)MROWS * DMODEL;
    const size_t NW = (size_t)DMODEL * DMODEL;
    const float* biases[3] = {bq, bk, bv};
    unsigned short* outs[3] = {g_Qh, g_Kh, g_Vh};
    const float scales[3] = {0.125f * LOG2E, 1.0f, 1.0f};
    gemm_core(g_Ih + (size_t)z * NI, g_Il + (size_t)z * NI,
              g_WhA + (size_t)z * NW, g_WlA + (size_t)z * NW,
              biases[z], nullptr, outs[z], scales[z], 1,
              blockIdx.y * 128, blockIdx.x * 128, gsm);
}

// O projection: fp32 out.
__global__ __launch_bounds__(256, 2) void gemm_o(const float* __restrict__ bo,
                                                 float* __restrict__ out)
{
    extern __shared__ char gsm[];
    const size_t NW = (size_t)DMODEL * DMODEL;
    gemm_core(g_Ah, g_Al, g_WhA + 3 * NW, g_WlA + 3 * NW,
              bo, out, nullptr, 1.0f, 0,
              blockIdx.y * 128, blockIdx.x * 128, gsm);
}

// ===========================================================================
// mma.sync attention — R16 verbatim (fp16 single-term, 4-stage, exp2 domain,
// bf16 hi/lo epilogue).
// ===========================================================================

#define OQH 0
#define OST 16384
#define STAGE_SZ 16384
#define SKH 0
#define SVH 8192
#define NSTAGE 4
#define ATTN_SMEM (OST + NSTAGE * STAGE_SZ)   /* 80 KB */
#define NKT (SEQ / 64)

__global__ __launch_bounds__(256, 2) void attn_kernel(
    const unsigned short* __restrict__ Qh,
    const unsigned short* __restrict__ Kh,
    const unsigned short* __restrict__ Vh,
    const float* __restrict__ relpos,
    unsigned short* __restrict__ Ah,
    unsigned short* __restrict__ Al)
{
    extern __shared__ char smp[];
    const uint32_t sb = smem_u32(smp);

    const int tid = threadIdx.x;
    const int w = tid >> 5;
    const int lane = tid & 31;
    const int b = blockIdx.z, h = blockIdx.y;
    const int q0 = blockIdx.x * 128;

    const float rb0 = relpos[h * 5 + 0] * LOG2E;
    const float rb1 = relpos[h * 5 + 1] * LOG2E;
    const float rb2 = relpos[h * 5 + 2] * LOG2E;
    const float rb3 = relpos[h * 5 + 3] * LOG2E;
    const float rb4 = relpos[h * 5 + 4] * LOG2E;

    {
        const int row = tid >> 1;
        const int ch0 = (tid & 1) * 4;
        const size_t gb = (size_t)(b * SEQ + q0 + row) * DMODEL + h * HDIM + ch0 * 8;
#pragma unroll
        for (int ci = 0; ci < 4; ci++) {
            const uint32_t off = SW128((uint32_t)(row * 128 + (ch0 + ci) * 16));
            *(uint4*)(smp + OQH + off) = *(const uint4*)(Qh + gb + ci * 8);
        }
    }

    const int krow = tid >> 2;
    const int kch = tid & 3;
    const size_t kgb0 = (size_t)(b * SEQ + krow) * DMODEL + h * HDIM + kch * 16;
    const uint32_t loff0 = SW128((uint32_t)(krow * 128 + kch * 32));
    const uint32_t loff1 = SW128((uint32_t)(krow * 128 + kch * 32 + 16));

#pragma unroll
    for (int s = 0; s < NSTAGE - 1; s++) {
        const uint32_t st = sb + OST + s * STAGE_SZ;
        const size_t gb = kgb0 + (size_t)(s * 64) * DMODEL;
        cpa16(st + SKH + loff0, Kh + gb);  cpa16(st + SKH + loff1, Kh + gb + 8);
        cpa16(st + SVH + loff0, Vh + gb);  cpa16(st + SVH + loff1, Vh + gb + 8);
        CP_COMMIT();
    }

    const uint32_t base_qa = (uint32_t)((16 * w + (lane & 15)) * 128 + 16 * (lane >> 4));
    const uint32_t base_kb = (uint32_t)(((lane & 7) + ((lane & 16) >> 1)) * 128 + ((lane >> 3) & 1) * 16);
    const uint32_t base_vb = (uint32_t)(((lane & 7) + (lane & 8)) * 128 + ((lane >> 4) & 1) * 16);

    float co[8][4];
#pragma unroll
    for (int i = 0; i < 8; i++)
#pragma unroll
        for (int j = 0; j < 4; j++) co[i][j] = 0.f;
    float sum0 = 0.f, sum1 = 0.f;

    const int r0g = q0 + 16 * w + (lane >> 2);
    const int kcol_off = 2 * (lane & 3);

    for (int kt = 0; kt < NKT; kt++) {
        const int k0 = kt * 64;

        CP_WAIT2();
        __syncthreads();

        if (kt + NSTAGE - 1 < NKT) {
            const uint32_t st = sb + OST + ((kt + NSTAGE - 1) % NSTAGE) * STAGE_SZ;
            const size_t gb = kgb0 + (size_t)((kt + NSTAGE - 1) * 64) * DMODEL;
            cpa16(st + SKH + loff0, Kh + gb);  cpa16(st + SKH + loff1, Kh + gb + 8);
            cpa16(st + SVH + loff0, Vh + gb);  cpa16(st + SVH + loff1, Vh + gb + 8);
        }
        CP_COMMIT();

        const uint32_t st = sb + OST + (kt % NSTAGE) * STAGE_SZ;
        const uint32_t KHb = st + SKH, VHb = st + SVH;
        const uint32_t QHb = sb + OQH;

        float cs[8][4];
#pragma unroll
        for (int i = 0; i < 8; i++)
#pragma unroll
            for (int j = 0; j < 4; j++) cs[i][j] = 0.f;

#pragma unroll
        for (int c = 0; c < 4; c++) {
            uint32_t ah[4];
            ldsm4(ah, QHb + SW128(base_qa + 32 * c));
#pragma unroll
            for (int j2 = 0; j2 < 4; j2++) {
                uint32_t bh[4];
                ldsm4(bh, KHb + SW128(base_kb + 2048u * j2 + 32u * c));
                mmaf16(cs[2 * j2], ah, bh[0], bh[1]);
                mmaf16(cs[2 * j2 + 1], ah, bh[2], bh[3]);
            }
        }

        const bool uni = (k0 - (q0 + 127) > MAXREL) || ((k0 + 63) - q0 < -MAXREL);
        if (uni) {
            const float ub = (k0 > q0) ? rb4 : rb0;
#pragma unroll
            for (int j = 0; j < 8; j++) {
                cs[j][0] = ex2f(cs[j][0] + ub);
                cs[j][1] = ex2f(cs[j][1] + ub);
                cs[j][2] = ex2f(cs[j][2] + ub);
                cs[j][3] = ex2f(cs[j][3] + ub);
            }
        } else {
#pragma unroll
            for (int j = 0; j < 8; j++) {
                const int kc = k0 + 8 * j + kcol_off;
#pragma unroll
                for (int i = 0; i < 4; i++) {
                    const int rel = (kc + (i & 1)) - (r0g + (i >> 1) * 8);
                    const float bb = rel <= -MAXREL ? rb0 :
                                     rel >= MAXREL ? rb4 :
                                     rel == -1 ? rb1 : (rel == 0 ? rb2 : rb3);
                    cs[j][i] = ex2f(cs[j][i] + bb);
                }
            }
        }
#pragma unroll
        for (int j = 0; j < 8; j++) {
            sum0 += cs[j][0] + cs[j][1];
            sum1 += cs[j][2] + cs[j][3];
        }

#pragma unroll
        for (int kc = 0; kc < 4; kc++) {
            uint32_t ph[4];
            ph[0] = pkhf2(cs[2 * kc][0],     cs[2 * kc][1]);
            ph[1] = pkhf2(cs[2 * kc][2],     cs[2 * kc][3]);
            ph[2] = pkhf2(cs[2 * kc + 1][0], cs[2 * kc + 1][1]);
            ph[3] = pkhf2(cs[2 * kc + 1][2], cs[2 * kc + 1][3]);
#pragma unroll
            for (int jv = 0; jv < 4; jv++) {
                uint32_t vh[4];
                ldsm4t(vh, VHb + SW128(base_vb + 2048u * kc + 32u * jv));
                mmaf16(co[2 * jv], ph, vh[0], vh[1]);
                mmaf16(co[2 * jv + 1], ph, vh[2], vh[3]);
            }
        }
    }

    sum0 += __shfl_xor_sync(0xFFFFFFFFu, sum0, 1);
    sum0 += __shfl_xor_sync(0xFFFFFFFFu, sum0, 2);
    sum1 += __shfl_xor_sync(0xFFFFFFFFu, sum1, 1);
    sum1 += __shfl_xor_sync(0xFFFFFFFFu, sum1, 2);
    const float inv0 = 1.0f / sum0;
    const float inv1 = 1.0f / sum1;

    {
        const size_t base0 = (size_t)(b * SEQ + r0g) * DMODEL + h * HDIM + kcol_off;
        const size_t base1 = base0 + (size_t)8 * DMODEL;
#pragma unroll
        for (int j = 0; j < 8; j++) {
            uint32_t hh, ll;
            split2(co[j][0] * inv0, co[j][1] * inv0, hh, ll);
            *(uint32_t*)(Ah + base0 + 8 * j) = hh;
            *(uint32_t*)(Al + base0 + 8 * j) = ll;
            split2(co[j][2] * inv1, co[j][3] * inv1, hh, ll);
            *(uint32_t*)(Ah + base1 + 8 * j) = hh;
            *(uint32_t*)(Al + base1 + 8 * j) = ll;
        }
    }
}

// ---------------------------------------------------------------------------
extern "C" void kernel_launch(void* const* d_in, const int* in_sizes, int n_in,
                              void* d_out, int out_size)
{
    const float* q  = (const float*)d_in[0];
    const float* k  = (const float*)d_in[1];
    const float* v  = (const float*)d_in[2];
    const float* Wq = (const float*)d_in[3];
    const float* bq = (const float*)d_in[4];
    const float* Wk = (const float*)d_in[5];
    const float* bk = (const float*)d_in[6];
    const float* Wv = (const float*)d_in[7];
    const float* bv = (const float*)d_in[8];
    const float* Wo = (const float*)d_in[9];
    const float* bo = (const float*)d_in[10];
    const float* rp = (const float*)d_in[11];
    float* out = (float*)d_out;

    unsigned short *dQh, *dKh, *dVh, *dAh, *dAl;
    cudaGetSymbolAddress((void**)&dQh, g_Qh);
    cudaGetSymbolAddress((void**)&dKh, g_Kh);
    cudaGetSymbolAddress((void**)&dVh, g_Vh);
    cudaGetSymbolAddress((void**)&dAh, g_Ah);
    cudaGetSymbolAddress((void**)&dAl, g_Al);

    cudaFuncSetAttribute(attn_kernel, cudaFuncAttributeMaxDynamicSharedMemorySize,
                         ATTN_SMEM);
    cudaFuncSetAttribute(gemm_qkv, cudaFuncAttributeMaxDynamicSharedMemorySize,
                         GEMM_SMEM);
    cudaFuncSetAttribute(gemm_o, cudaFuncAttributeMaxDynamicSharedMemorySize,
                         GEMM_SMEM);

    dim3 gblk(256);

    split_x3<<<dim3(MROWS * DMODEL / 4 / 256, 3), gblk>>>(q, k, v);
    split_w4<<<dim3(DMODEL * DMODEL / 4 / 256, 4), gblk>>>(Wq, Wk, Wv, Wo);

    gemm_qkv<<<dim3(DMODEL / 128, MROWS / 128, 3), gblk, GEMM_SMEM>>>(bq, bk, bv);

    dim3 agrid(SEQ / 128, NHEAD, BATCH);     // (32, 8, 2)
    attn_kernel<<<agrid, gblk, ATTN_SMEM>>>(dQh, dKh, dVh, rp, dAh, dAl);

    gemm_o<<<dim3(DMODEL / 128, MROWS / 128), gblk, GEMM_SMEM>>>(bo, out);
}